// round 5
// baseline (speedup 1.0000x reference)
#include <cuda_runtime.h>
#include <cstdint>

#define SPATIAL 131072   // D*H*W per (batch, channel)
#define HW2     16384    // H*W

// Scratch (no allocations allowed anywhere)
__device__ float g_h [2 * 64 * SPATIAL];
__device__ float g_uv[2 * 64 * SPATIAL];
__device__ float g_vp[2 * 3  * SPATIAL];

typedef unsigned long long u64;

__device__ __forceinline__ u64 pack_dup(float x) {
    u64 u; asm("mov.b64 %0, {%1, %2};" : "=l"(u) : "f"(x), "f"(x)); return u;
}
__device__ __forceinline__ u64 pack2(float a, float b) {
    u64 u; asm("mov.b64 %0, {%1, %2};" : "=l"(u) : "f"(a), "f"(b)); return u;
}
__device__ __forceinline__ void fma2(u64& d, u64 a, u64 b) {
    asm("fma.rn.f32x2 %0, %1, %2, %0;" : "+l"(d) : "l"(a), "l"(b));
}
__device__ __forceinline__ float2 unpk(u64 v) {
    float2 f; asm("mov.b64 {%0, %1}, %2;" : "=f"(f.x), "=f"(f.y) : "l"(v)); return f;
}

// ---------------------------------------------------------------------------
// EXACT R2 GEMM (known good): C[b][m][p] = sum_k A[m][k] * X[b][k][p]
// CTA tile 64 x 256, thread tile 8m x 8n, packed f32x2 FMAs.
// VP_EPI: also Vp[b][r][p] = sum_m Vw[m][r] * C[m][p] (head only).
// ---------------------------------------------------------------------------
template<bool VP_EPI>
__device__ __forceinline__ void gemm64_body(const float* __restrict__ X,
                                            const float* __restrict__ A,
                                            float* __restrict__ C,
                                            const float* __restrict__ Vw) {
    extern __shared__ float Bs[];            // 64 * 256 floats = 64 KB
    __shared__ float As[64 * 64];            // As[k*64 + m] = A[m][k]
    const int t  = threadIdx.x;
    const int b  = blockIdx.y;
    const int p0 = blockIdx.x * 256;
    const float* Xb = X + b * (64 * SPATIAL);

#pragma unroll
    for (int i = 0; i < 4; ++i) {            // A transposed
        int fl = t + 256 * i;                // 1024 float4s
        int m = fl >> 4, kq = fl & 15;
        float4 v = *reinterpret_cast<const float4*>(A + m * 64 + kq * 4);
        As[(kq * 4 + 0) * 64 + m] = v.x;
        As[(kq * 4 + 1) * 64 + m] = v.y;
        As[(kq * 4 + 2) * 64 + m] = v.z;
        As[(kq * 4 + 3) * 64 + m] = v.w;
    }
#pragma unroll
    for (int i = 0; i < 16; ++i) {           // B tile 64 x 256
        int fl = t + 256 * i;                // 4096 float4s
        int k = fl >> 6, cq = fl & 63;
        *reinterpret_cast<float4*>(Bs + k * 256 + cq * 4) =
            *reinterpret_cast<const float4*>(Xb + k * SPATIAL + p0 + cq * 4);
    }
    __syncthreads();

    const int cg = t & 31;      // cols cg*8 .. cg*8+7
    const int rg = t >> 5;      // rows rg*8 .. rg*8+7
    u64 acc[32];
#pragma unroll
    for (int i = 0; i < 32; ++i) acc[i] = 0ull;

#pragma unroll 4
    for (int k = 0; k < 64; ++k) {
        float4 a0 = *reinterpret_cast<const float4*>(As + k * 64 + rg * 8);
        float4 a1 = *reinterpret_cast<const float4*>(As + k * 64 + rg * 8 + 4);
        float4 b0 = *reinterpret_cast<const float4*>(Bs + k * 256 + cg * 8);
        float4 b1 = *reinterpret_cast<const float4*>(Bs + k * 256 + cg * 8 + 4);
        u64 bp0 = pack2(b0.x, b0.y), bp1 = pack2(b0.z, b0.w);
        u64 bp2 = pack2(b1.x, b1.y), bp3 = pack2(b1.z, b1.w);
        float am[8] = {a0.x, a0.y, a0.z, a0.w, a1.x, a1.y, a1.z, a1.w};
#pragma unroll
        for (int j = 0; j < 8; ++j) {
            u64 aj = pack_dup(am[j]);
            fma2(acc[j * 4 + 0], aj, bp0);
            fma2(acc[j * 4 + 1], aj, bp1);
            fma2(acc[j * 4 + 2], aj, bp2);
            fma2(acc[j * 4 + 3], aj, bp3);
        }
    }

    float* Cb = C + b * (64 * SPATIAL);
#pragma unroll
    for (int j = 0; j < 8; ++j) {
        float2 q0 = unpk(acc[j * 4 + 0]), q1 = unpk(acc[j * 4 + 1]);
        float2 q2 = unpk(acc[j * 4 + 2]), q3 = unpk(acc[j * 4 + 3]);
        float* dst = Cb + (rg * 8 + j) * SPATIAL + p0 + cg * 8;
        *reinterpret_cast<float4*>(dst)     = make_float4(q0.x, q0.y, q1.x, q1.y);
        *reinterpret_cast<float4*>(dst + 4) = make_float4(q2.x, q2.y, q3.x, q3.y);
    }

    if (VP_EPI) {
        u64 pvp[3][4];
#pragma unroll
        for (int r = 0; r < 3; ++r)
#pragma unroll
            for (int q = 0; q < 4; ++q) pvp[r][q] = 0ull;
#pragma unroll
        for (int j = 0; j < 8; ++j) {
            int m = rg * 8 + j;
#pragma unroll
            for (int r = 0; r < 3; ++r) {
                u64 vw = pack_dup(__ldg(&Vw[m * 3 + r]));
                fma2(pvp[r][0], vw, acc[j * 4 + 0]);
                fma2(pvp[r][1], vw, acc[j * 4 + 1]);
                fma2(pvp[r][2], vw, acc[j * 4 + 2]);
                fma2(pvp[r][3], vw, acc[j * 4 + 3]);
            }
        }
        __syncthreads();                      // Bs reads done -> reuse as vred
        float* vred = Bs;                     // [rowg 8][r 3][col 256]
#pragma unroll
        for (int r = 0; r < 3; ++r)
#pragma unroll
            for (int q = 0; q < 4; ++q)
                *reinterpret_cast<float2*>(vred + (rg * 3 + r) * 256 + cg * 8 + q * 2)
                    = unpk(pvp[r][q]);
        __syncthreads();
#pragma unroll
        for (int i = 0; i < 3; ++i) {
            int idx = t + 256 * i;            // 768 outputs
            int r = idx >> 8, col = idx & 255;
            float s = 0.f;
#pragma unroll
            for (int g = 0; g < 8; ++g) s += vred[(g * 3 + r) * 256 + col];
            g_vp[(b * 3 + r) * SPATIAL + p0 + col] = s;
        }
    }
}

__global__ void __launch_bounds__(256) gemm_head(const float* __restrict__ X,
                                                 const float* __restrict__ A,
                                                 const float* __restrict__ Vw) {
    gemm64_body<true>(X, A, g_h, Vw);
}
__global__ void __launch_bounds__(256) gemm_tail(const float* __restrict__ A,
                                                 float* __restrict__ C) {
    gemm64_body<false>(g_uv, A, C, nullptr);
}

// ---------------------------------------------------------------------------
// Fused middle: replicate-pad + depthwise 3x3x3 (3 ranks) + L2 norm over
// ranks + UV contraction with precomputed Vp.
// CTA = 1 channel, ALL 8 d planes, 8 h-rows, 128 w. 512 threads.
// smem holds the full 8-plane x 10-row x 130 halo tile (d read exactly once).
// Direct-indexed taps (no register sliding); weights hoisted per kz.
// ---------------------------------------------------------------------------
#define TW 136    // tile row stride in floats

__global__ void __launch_bounds__(512) midkernel(const float* __restrict__ Uw) {
    __shared__ __align__(16) float tile[8 * 10 * TW];  // [dz][hy][j], j = w+1
    __shared__ u64 uws2[81];                           // duplicated weight pairs
    const int t  = threadIdx.x;
    const int h0 = blockIdx.x * 8;
    const int c  = blockIdx.y;
    const int b  = blockIdx.z;
    const float* Hc = g_h + (b * 64 + c) * SPATIAL;

    if (t < 81) uws2[t] = pack_dup(Uw[t]);

    // ---- load halo tile: 80 rows (8 dz x 10 hy) x 130 floats ----
    {
        const int warp = t >> 5, lane = t & 31;
#pragma unroll
        for (int rr = 0; rr < 5; ++rr) {
            int row = warp + rr * 16;          // 0..79
            int dz = row / 10, hy = row - dz * 10;
            int gh = min(max(h0 + hy - 1, 0), 127);
            const float* src = Hc + dz * HW2 + gh * 128;
            float* dst = &tile[row * TW];
#pragma unroll
            for (int q = 0; q < 5; ++q) {
                int j = lane + q * 32;
                if (j < 130) dst[j] = src[min(max(j - 1, 0), 127)];
            }
        }
    }
    __syncthreads();

    const int d  = t >> 6;          // 0..7
    const int wp = t & 63;
    const int w  = wp * 2;          // output pair (w, w+1); tile j=w -> in[w-1]
    const int zr0 = max(d - 1, 0) * 10;
    const int zr1 = d * 10;
    const int zr2 = min(d + 1, 7) * 10;
    float* UVc = g_uv + (b * 64 + c) * SPATIAL;
    const float* vpb0 = g_vp + (b * 3 + 0) * SPATIAL;
    const float* vpb1 = g_vp + (b * 3 + 1) * SPATIAL;
    const float* vpb2 = g_vp + (b * 3 + 2) * SPATIAL;

#pragma unroll
    for (int hb = 0; hb < 2; ++hb) {            // two blocks of 4 output rows
        u64 acc[4][3];
#pragma unroll
        for (int i = 0; i < 4; ++i)
#pragma unroll
            for (int r = 0; r < 3; ++r) acc[i][r] = 0ull;

#pragma unroll
        for (int kz = 0; kz < 3; ++kz) {
            const int zro = (kz == 0) ? zr0 : ((kz == 1) ? zr1 : zr2);
            u64 wk[27];
#pragma unroll
            for (int j = 0; j < 27; ++j) wk[j] = uws2[kz * 27 + j];

#pragma unroll
            for (int i = 0; i < 4; ++i) {       // output row h0 + hb*4 + i
#pragma unroll
                for (int khy = 0; khy < 3; ++khy) {
                    const float* p = &tile[(zro + hb * 4 + i + khy) * TW + w];
                    u64 v01 = *reinterpret_cast<const u64*>(p);
                    u64 v23 = *reinterpret_cast<const u64*>(p + 2);
                    float2 f01 = unpk(v01), f23 = unpk(v23);
                    u64 v12 = pack2(f01.y, f23.x);
                    const u64* wt = &wk[khy * 9];
                    fma2(acc[i][0], v01, wt[0]);
                    fma2(acc[i][1], v01, wt[1]);
                    fma2(acc[i][2], v01, wt[2]);
                    fma2(acc[i][0], v12, wt[3]);
                    fma2(acc[i][1], v12, wt[4]);
                    fma2(acc[i][2], v12, wt[5]);
                    fma2(acc[i][0], v23, wt[6]);
                    fma2(acc[i][1], v23, wt[7]);
                    fma2(acc[i][2], v23, wt[8]);
                }
            }
        }

        // normalize over ranks, contract with Vp, store
#pragma unroll
        for (int i = 0; i < 4; ++i) {
            int sp = d * HW2 + (h0 + hb * 4 + i) * 128 + w;
            float2 q0 = unpk(acc[i][0]), q1 = unpk(acc[i][1]), q2 = unpk(acc[i][2]);
            float2 w0 = *reinterpret_cast<const float2*>(vpb0 + sp);
            float2 w1 = *reinterpret_cast<const float2*>(vpb1 + sp);
            float2 w2 = *reinterpret_cast<const float2*>(vpb2 + sp);
            float sa = q0.x * q0.x + q1.x * q1.x + q2.x * q2.x;
            float sb = q0.y * q0.y + q1.y * q1.y + q2.y * q2.y;
            float ia = __fdividef(1.0f, 1e-6f + sqrtf(sa));
            float ib = __fdividef(1.0f, 1e-6f + sqrtf(sb));
            float oa = ia * (q0.x * w0.x + q1.x * w1.x + q2.x * w2.x);
            float ob = ib * (q0.y * w0.y + q1.y * w1.y + q2.y * w2.y);
            *reinterpret_cast<float2*>(UVc + sp) = make_float2(oa, ob);
        }
    }
}

// ---------------------------------------------------------------------------
extern "C" void kernel_launch(void* const* d_in, const int* in_sizes, int n_in,
                              void* d_out, int out_size) {
    const float* x      = (const float*)d_in[0];
    const float* head_w = (const float*)d_in[1];
    const float* tail_w = (const float*)d_in[2];
    const float* Uw     = (const float*)d_in[3];
    const float* Vw     = (const float*)d_in[4];
    float* out = (float*)d_out;

    cudaFuncSetAttribute(gemm_head, cudaFuncAttributeMaxDynamicSharedMemorySize, 65536);
    cudaFuncSetAttribute(gemm_tail, cudaFuncAttributeMaxDynamicSharedMemorySize, 65536);

    dim3 gg(SPATIAL / 256, 2);
    gemm_head<<<gg, 256, 65536>>>(x, head_w, Vw);       // h + Vp
    midkernel<<<dim3(16, 64, 2), 512>>>(Uw);            // UV (fused middle)
    gemm_tail<<<gg, 256, 65536>>>(tail_w, out);         // out
}

// round 7
// speedup vs baseline: 1.2565x; 1.2565x over previous
#include <cuda_runtime.h>
#include <cstdint>

#define SPATIAL 131072   // D*H*W per (batch, channel)
#define HW2     16384    // H*W
#define TW      136      // mid tile row stride (floats)

// Scratch (no allocations allowed anywhere)
__device__ float g_h [2 * 64 * SPATIAL];
__device__ float g_uv[2 * 64 * SPATIAL];
__device__ float g_vp[2 * 3  * SPATIAL];

typedef unsigned long long u64;

__device__ __forceinline__ u64 pack_dup(float x) {
    u64 u; asm("mov.b64 %0, {%1, %2};" : "=l"(u) : "f"(x), "f"(x)); return u;
}
__device__ __forceinline__ u64 pack2(float a, float b) {
    u64 u; asm("mov.b64 %0, {%1, %2};" : "=l"(u) : "f"(a), "f"(b)); return u;
}
__device__ __forceinline__ void fma2(u64& d, u64 a, u64 b) {
    asm("fma.rn.f32x2 %0, %1, %2, %0;" : "+l"(d) : "l"(a), "l"(b));
}
__device__ __forceinline__ float2 unpk(u64 v) {
    float2 f; asm("mov.b64 {%0, %1}, %2;" : "=f"(f.x), "=f"(f.y) : "l"(v)); return f;
}

// ---------------------------------------------------------------------------
// KNOWN-GOOD GEMM (passed R2/R5): C[b][m][p] = sum_k A[m][k] * X[b][k][p]
// CTA tile 64 x 256, thread tile 8m x 8n, packed f32x2 FMAs.
// VP_EPI: also Vp[b][r][p] = sum_m Vw[m][r] * C[m][p] (head only).
// ---------------------------------------------------------------------------
template<bool VP_EPI>
__device__ __forceinline__ void gemm64_body(const float* __restrict__ X,
                                            const float* __restrict__ A,
                                            float* __restrict__ C,
                                            const float* __restrict__ Vw) {
    extern __shared__ float Bs[];            // 64 * 256 floats = 64 KB
    __shared__ float As[64 * 64];            // As[k*64 + m] = A[m][k]
    const int t  = threadIdx.x;
    const int b  = blockIdx.y;
    const int p0 = blockIdx.x * 256;
    const float* Xb = X + b * (64 * SPATIAL);

#pragma unroll
    for (int i = 0; i < 4; ++i) {            // A transposed
        int fl = t + 256 * i;                // 1024 float4s
        int m = fl >> 4, kq = fl & 15;
        float4 v = *reinterpret_cast<const float4*>(A + m * 64 + kq * 4);
        As[(kq * 4 + 0) * 64 + m] = v.x;
        As[(kq * 4 + 1) * 64 + m] = v.y;
        As[(kq * 4 + 2) * 64 + m] = v.z;
        As[(kq * 4 + 3) * 64 + m] = v.w;
    }
#pragma unroll
    for (int i = 0; i < 16; ++i) {           // B tile 64 x 256
        int fl = t + 256 * i;                // 4096 float4s
        int k = fl >> 6, cq = fl & 63;
        *reinterpret_cast<float4*>(Bs + k * 256 + cq * 4) =
            *reinterpret_cast<const float4*>(Xb + k * SPATIAL + p0 + cq * 4);
    }
    __syncthreads();

    const int cg = t & 31;      // cols cg*8 .. cg*8+7
    const int rg = t >> 5;      // rows rg*8 .. rg*8+7
    u64 acc[32];
#pragma unroll
    for (int i = 0; i < 32; ++i) acc[i] = 0ull;

#pragma unroll 4
    for (int k = 0; k < 64; ++k) {
        float4 a0 = *reinterpret_cast<const float4*>(As + k * 64 + rg * 8);
        float4 a1 = *reinterpret_cast<const float4*>(As + k * 64 + rg * 8 + 4);
        float4 b0 = *reinterpret_cast<const float4*>(Bs + k * 256 + cg * 8);
        float4 b1 = *reinterpret_cast<const float4*>(Bs + k * 256 + cg * 8 + 4);
        u64 bp0 = pack2(b0.x, b0.y), bp1 = pack2(b0.z, b0.w);
        u64 bp2 = pack2(b1.x, b1.y), bp3 = pack2(b1.z, b1.w);
        float am[8] = {a0.x, a0.y, a0.z, a0.w, a1.x, a1.y, a1.z, a1.w};
#pragma unroll
        for (int j = 0; j < 8; ++j) {
            u64 aj = pack_dup(am[j]);
            fma2(acc[j * 4 + 0], aj, bp0);
            fma2(acc[j * 4 + 1], aj, bp1);
            fma2(acc[j * 4 + 2], aj, bp2);
            fma2(acc[j * 4 + 3], aj, bp3);
        }
    }

    float* Cb = C + b * (64 * SPATIAL);
#pragma unroll
    for (int j = 0; j < 8; ++j) {
        float2 q0 = unpk(acc[j * 4 + 0]), q1 = unpk(acc[j * 4 + 1]);
        float2 q2 = unpk(acc[j * 4 + 2]), q3 = unpk(acc[j * 4 + 3]);
        float* dst = Cb + (rg * 8 + j) * SPATIAL + p0 + cg * 8;
        *reinterpret_cast<float4*>(dst)     = make_float4(q0.x, q0.y, q1.x, q1.y);
        *reinterpret_cast<float4*>(dst + 4) = make_float4(q2.x, q2.y, q3.x, q3.y);
    }

    if (VP_EPI) {
        u64 pvp[3][4];
#pragma unroll
        for (int r = 0; r < 3; ++r)
#pragma unroll
            for (int q = 0; q < 4; ++q) pvp[r][q] = 0ull;
#pragma unroll
        for (int j = 0; j < 8; ++j) {
            int m = rg * 8 + j;
#pragma unroll
            for (int r = 0; r < 3; ++r) {
                u64 vw = pack_dup(__ldg(&Vw[m * 3 + r]));
                fma2(pvp[r][0], vw, acc[j * 4 + 0]);
                fma2(pvp[r][1], vw, acc[j * 4 + 1]);
                fma2(pvp[r][2], vw, acc[j * 4 + 2]);
                fma2(pvp[r][3], vw, acc[j * 4 + 3]);
            }
        }
        __syncthreads();                      // Bs reads done -> reuse as vred
        float* vred = Bs;                     // [rowg 8][r 3][col 256]
#pragma unroll
        for (int r = 0; r < 3; ++r)
#pragma unroll
            for (int q = 0; q < 4; ++q)
                *reinterpret_cast<float2*>(vred + (rg * 3 + r) * 256 + cg * 8 + q * 2)
                    = unpk(pvp[r][q]);
        __syncthreads();
#pragma unroll
        for (int i = 0; i < 3; ++i) {
            int idx = t + 256 * i;            // 768 outputs
            int r = idx >> 8, col = idx & 255;
            float s = 0.f;
#pragma unroll
            for (int g = 0; g < 8; ++g) s += vred[(g * 3 + r) * 256 + col];
            g_vp[(b * 3 + r) * SPATIAL + p0 + col] = s;
        }
    }
}

__global__ void __launch_bounds__(256) gemm_head(const float* __restrict__ X,
                                                 const float* __restrict__ A,
                                                 const float* __restrict__ Vw) {
    gemm64_body<true>(X, A, g_h, Vw);
}
__global__ void __launch_bounds__(256) gemm_tail(const float* __restrict__ A,
                                                 float* __restrict__ C) {
    gemm64_body<false>(g_uv, A, C, nullptr);
}

// ---------------------------------------------------------------------------
// Fused middle (R6 restructure, SOLE change under test this round):
// replicate-pad + depthwise 3x3x3 (3 ranks) + L2 norm + UV with precomputed Vp.
// CTA = 1 channel x all 8 d x 4 h-rows x 128 w. 512 threads, 2 CTAs/SM.
// Weights staged 9 pairs at a time (low register pressure).
// ---------------------------------------------------------------------------
__global__ void __launch_bounds__(512, 2) midkernel(const float* __restrict__ Uw) {
    __shared__ __align__(16) float tile[8 * 6 * TW];   // [dz][hy 0..5][j], j = w+1
    __shared__ u64 uws2[81];
    const int t  = threadIdx.x;
    const int h0 = blockIdx.x * 4;
    const int c  = blockIdx.y;
    const int b  = blockIdx.z;
    const float* Hc = g_h + (b * 64 + c) * SPATIAL;

    if (t < 81) uws2[t] = pack_dup(Uw[t]);

    // ---- load halo tile: 48 rows (8 dz x 6 hy) x 130 floats ----
    {
        const int warp = t >> 5, lane = t & 31;
#pragma unroll
        for (int rr = 0; rr < 3; ++rr) {
            int row = warp + rr * 16;          // 0..47
            int dz = row / 6, hy = row - dz * 6;
            int gh = min(max(h0 + hy - 1, 0), 127);
            const float* src = Hc + dz * HW2 + gh * 128;
            float* dst = &tile[row * TW];
#pragma unroll
            for (int q = 0; q < 5; ++q) {
                int j = lane + q * 32;
                if (j < 130) dst[j] = src[min(max(j - 1, 0), 127)];
            }
        }
    }
    __syncthreads();

    const int d  = t >> 6;          // 0..7
    const int wp = t & 63;
    const int w  = wp * 2;          // output pair; tile j=w holds in[w-1]
    const int zb0 = max(d - 1, 0) * 6;
    const int zb1 = d * 6;
    const int zb2 = min(d + 1, 7) * 6;

    u64 acc[4][3];
#pragma unroll
    for (int i = 0; i < 4; ++i)
#pragma unroll
        for (int r = 0; r < 3; ++r) acc[i][r] = 0ull;

#pragma unroll
    for (int kz = 0; kz < 3; ++kz) {
        const int zro = (kz == 0) ? zb0 : ((kz == 1) ? zb1 : zb2);
#pragma unroll
        for (int khy = 0; khy < 3; ++khy) {
            u64 wt[9];
#pragma unroll
            for (int j = 0; j < 9; ++j) wt[j] = uws2[kz * 27 + khy * 9 + j];
#pragma unroll
            for (int i = 0; i < 4; ++i) {       // output row h0 + i
                const float* p = &tile[(zro + i + khy) * TW + w];
                u64 v01 = *reinterpret_cast<const u64*>(p);
                u64 v23 = *reinterpret_cast<const u64*>(p + 2);
                float2 f01 = unpk(v01), f23 = unpk(v23);
                u64 v12 = pack2(f01.y, f23.x);
                fma2(acc[i][0], v01, wt[0]);
                fma2(acc[i][1], v01, wt[1]);
                fma2(acc[i][2], v01, wt[2]);
                fma2(acc[i][0], v12, wt[3]);
                fma2(acc[i][1], v12, wt[4]);
                fma2(acc[i][2], v12, wt[5]);
                fma2(acc[i][0], v23, wt[6]);
                fma2(acc[i][1], v23, wt[7]);
                fma2(acc[i][2], v23, wt[8]);
            }
        }
    }

    // ---- normalize over ranks, contract with Vp, store ----
    float* UVc = g_uv + (b * 64 + c) * SPATIAL;
    const float* vpb0 = g_vp + (b * 3 + 0) * SPATIAL;
    const float* vpb1 = g_vp + (b * 3 + 1) * SPATIAL;
    const float* vpb2 = g_vp + (b * 3 + 2) * SPATIAL;
#pragma unroll
    for (int i = 0; i < 4; ++i) {
        int sp = d * HW2 + (h0 + i) * 128 + w;
        float2 q0 = unpk(acc[i][0]), q1 = unpk(acc[i][1]), q2 = unpk(acc[i][2]);
        float2 w0 = *reinterpret_cast<const float2*>(vpb0 + sp);
        float2 w1 = *reinterpret_cast<const float2*>(vpb1 + sp);
        float2 w2 = *reinterpret_cast<const float2*>(vpb2 + sp);
        float sa = q0.x * q0.x + q1.x * q1.x + q2.x * q2.x;
        float sb = q0.y * q0.y + q1.y * q1.y + q2.y * q2.y;
        float ia = __fdividef(1.0f, 1e-6f + sqrtf(sa));
        float ib = __fdividef(1.0f, 1e-6f + sqrtf(sb));
        float oa = ia * (q0.x * w0.x + q1.x * w1.x + q2.x * w2.x);
        float ob = ib * (q0.y * w0.y + q1.y * w1.y + q2.y * w2.y);
        *reinterpret_cast<float2*>(UVc + sp) = make_float2(oa, ob);
    }
}

// ---------------------------------------------------------------------------
extern "C" void kernel_launch(void* const* d_in, const int* in_sizes, int n_in,
                              void* d_out, int out_size) {
    const float* x      = (const float*)d_in[0];
    const float* head_w = (const float*)d_in[1];
    const float* tail_w = (const float*)d_in[2];
    const float* Uw     = (const float*)d_in[3];
    const float* Vw     = (const float*)d_in[4];
    float* out = (float*)d_out;

    cudaFuncSetAttribute(gemm_head, cudaFuncAttributeMaxDynamicSharedMemorySize, 65536);
    cudaFuncSetAttribute(gemm_tail, cudaFuncAttributeMaxDynamicSharedMemorySize, 65536);

    dim3 gg(SPATIAL / 256, 2);
    gemm_head<<<gg, 256, 65536>>>(x, head_w, Vw);       // h + Vp
    midkernel<<<dim3(32, 64, 2), 512>>>(Uw);            // UV (fused middle)
    gemm_tail<<<gg, 256, 65536>>>(tail_w, out);         // out
}